// round 1
// baseline (speedup 1.0000x reference)
#include <cuda_runtime.h>
#include <math.h>

#define Bn 128
#define Ln 1024
#define Vn 32
#define En 256
#define Hn 1024

#define G 128          // persistent CTAs (must all be co-resident)
#define KS 16          // K splits
#define KC 64          // K chunk = Hn/KS
#define CGn 8          // column groups
#define CT 128         // column tile = Hn/CGn
#define NT 256         // threads per CTA
#define SA_PITCH 132   // padded pitch for transposed h staging

// ---- device scratch (no allocations allowed) ----
__device__ float g_P[Vn * Hn];                 // 128 KB: embedding@W_e + b_h
__device__ float g_h[2][Bn * Hn];              // 1 MB: double-buffered hidden
__device__ float g_part[KS][Bn][Hn];           // 8 MB: split-K partials
__device__ unsigned g_arrive[G];               // barrier flags (monotonic tokens)

// smem layout (floats)
#define SW_SZ   (KC * CT)        // 8192  : W_h slice (persistent)
#define SA_SZ   (KC * SA_PITCH)  // 8448  : transposed h chunk
#define SWO_SZ  (Hn * Vn)        // 32768 : W_o (persistent)
#define HROW_SZ (Hn)             // 1024  : hnew row for logits
#define RED_SZ  (8 * Vn)         // 256   : logits reduction
#define SMEM_FLOATS (SW_SZ + SA_SZ + SWO_SZ + HROW_SZ + RED_SZ)
#define SMEM_BYTES  (SMEM_FLOATS * 4)

// ---- packed f32x2 helpers (Blackwell FFMA2 path) ----
__device__ __forceinline__ unsigned long long ffma2(unsigned long long a,
                                                    unsigned long long b,
                                                    unsigned long long c) {
    unsigned long long d;
    asm("fma.rn.f32x2 %0, %1, %2, %3;" : "=l"(d) : "l"(a), "l"(b), "l"(c));
    return d;
}
__device__ __forceinline__ unsigned long long dup2(float x) {
    unsigned long long r;
    asm("mov.b64 %0, {%1, %1};" : "=l"(r) : "f"(x));
    return r;
}
__device__ __forceinline__ void unpk2(unsigned long long v, float& lo, float& hi) {
    asm("mov.b64 {%0, %1}, %2;" : "=f"(lo), "=f"(hi) : "l"(v));
}

// ---- device-scope acquire/release for the grid barrier ----
__device__ __forceinline__ void relstore(unsigned* p, unsigned v) {
    asm volatile("st.release.gpu.u32 [%0], %1;" :: "l"(p), "r"(v) : "memory");
}
__device__ __forceinline__ unsigned acqload(const unsigned* p) {
    unsigned v;
    asm volatile("ld.acquire.gpu.u32 %0, [%1];" : "=r"(v) : "l"(p) : "memory");
    return v;
}

// Grid barrier: monotonic token, distributed flags. Safe across graph replays
// because each CTA derives its token base from its own (globally equal) slot.
__device__ __forceinline__ void gridbar(unsigned token) {
    __syncthreads();
    if (threadIdx.x == 0) relstore(&g_arrive[blockIdx.x], token);
    if (threadIdx.x < G) {
        const unsigned* p = &g_arrive[threadIdx.x];
        unsigned v = acqload(p);
        while ((int)(v - token) < 0) { __nanosleep(40); v = acqload(p); }
    }
    __syncthreads();
}

// ---- kernel A: P = embedding @ W_e + b_h ----
__global__ void precompute_P(const float* __restrict__ emb,
                             const float* __restrict__ We,
                             const float* __restrict__ bh) {
    int v = blockIdx.x;
    int h = threadIdx.x;   // 1024 threads
    float acc = bh[h];
    const float* er = emb + v * En;
#pragma unroll 8
    for (int e = 0; e < En; ++e) acc = fmaf(er[e], We[e * Hn + h], acc);
    g_P[v * Hn + h] = acc;
}

// ---- kernel B: copy initial hidden state ----
__global__ void init_h(const float* __restrict__ hidden) {
    int i = blockIdx.x * blockDim.x + threadIdx.x;
    g_h[0][i] = hidden[i];
}

// ---- kernel C: persistent RNN ----
__global__ void __launch_bounds__(NT, 1)
rnn_kernel(const int* __restrict__ x,
           const float* __restrict__ Wh,
           const float* __restrict__ Wo,
           const float* __restrict__ bo,
           float* __restrict__ logits,
           float* __restrict__ outh) {
    extern __shared__ float smem[];
    float* sW   = smem;                 // [KC][CT]
    float* sA   = sW + SW_SZ;           // [KC][SA_PITCH] transposed h chunk
    float* sWo  = sA + SA_SZ;           // [Hn][Vn]
    float* hrow = sWo + SWO_SZ;         // [Hn]
    float* red  = hrow + HROW_SZ;       // [8][Vn]

    const int tid = threadIdx.x;
    const int bid = blockIdx.x;
    const int ks  = bid >> 3;           // 0..15
    const int cg  = bid & 7;            // 0..7
    const int ty  = tid >> 4;           // 0..15 (row group of 8)
    const int tx  = tid & 15;           // 0..15 (col group of 8)

    // persistent smem loads (once per launch)
    for (int i = tid; i < SW_SZ; i += NT) {
        int k = i >> 7, j = i & 127;
        sW[i] = Wh[(ks * KC + k) * Hn + cg * CT + j];
    }
    for (int i = tid; i < SWO_SZ; i += NT) sWo[i] = Wo[i];

    unsigned token = acqload(&g_arrive[bid]);   // all slots equal at launch

    const float* hcur = g_h[0];
    float*       hnxt = g_h[1];

    for (int l = 0; l < Ln; ++l) {
        // ================= phase 1: partial GEMM h @ W_h (this K-chunk) ======
        // stage sA[k][b] = hcur[b][ks*KC + k]  (transposed, padded)
#pragma unroll
        for (int i = 0; i < (Bn * KC) / NT; ++i) {
            int idx = tid + i * NT;
            int b  = idx >> 6;
            int kk = idx & 63;
            sA[kk * SA_PITCH + b] = hcur[b * Hn + ks * KC + kk];
        }
        __syncthreads();

        unsigned long long acc[4][8];
#pragma unroll
        for (int rp = 0; rp < 4; ++rp)
#pragma unroll
            for (int c = 0; c < 8; ++c) acc[rp][c] = 0ull;

#pragma unroll 2
        for (int k = 0; k < KC; ++k) {
            const ulonglong2* ap =
                reinterpret_cast<const ulonglong2*>(sA + k * SA_PITCH + ty * 8);
            ulonglong2 a01 = ap[0];
            ulonglong2 a23 = ap[1];
            unsigned long long aa0 = a01.x, aa1 = a01.y, aa2 = a23.x, aa3 = a23.y;
            const float4* bp =
                reinterpret_cast<const float4*>(sW + k * CT + tx * 8);
            float4 bv0 = bp[0], bv1 = bp[1];
            float bw[8] = {bv0.x, bv0.y, bv0.z, bv0.w, bv1.x, bv1.y, bv1.z, bv1.w};
#pragma unroll
            for (int c = 0; c < 8; ++c) {
                unsigned long long bd = dup2(bw[c]);
                acc[0][c] = ffma2(aa0, bd, acc[0][c]);
                acc[1][c] = ffma2(aa1, bd, acc[1][c]);
                acc[2][c] = ffma2(aa2, bd, acc[2][c]);
                acc[3][c] = ffma2(aa3, bd, acc[3][c]);
            }
        }

        // write partials: rows ty*8 + rp*2 (+1), cols cg*CT + tx*8 .. +8
        {
            int r0 = ty * 8;
            int jc = cg * CT + tx * 8;
#pragma unroll
            for (int rp = 0; rp < 4; ++rp) {
                float lo[8], hi[8];
#pragma unroll
                for (int c = 0; c < 8; ++c) unpk2(acc[rp][c], lo[c], hi[c]);
                float* d0 = &g_part[ks][r0 + rp * 2][jc];
                float* d1 = &g_part[ks][r0 + rp * 2 + 1][jc];
                ((float4*)d0)[0] = make_float4(lo[0], lo[1], lo[2], lo[3]);
                ((float4*)d0)[1] = make_float4(lo[4], lo[5], lo[6], lo[7]);
                ((float4*)d1)[0] = make_float4(hi[0], hi[1], hi[2], hi[3]);
                ((float4*)d1)[1] = make_float4(hi[4], hi[5], hi[6], hi[7]);
            }
        }

        ++token;
        gridbar(token);

        // ================= phase 2: reduce + tanh + logits (row b = bid) =====
        {
            const int b  = bid;
            const int xv = x[b * Ln + l];
            const float* Prow = g_P + xv * Hn;
            const int h0 = tid * 4;

            float4 s = *(const float4*)(Prow + h0);
#pragma unroll
            for (int ksi = 0; ksi < KS; ++ksi) {
                float4 p = *(const float4*)(&g_part[ksi][b][h0]);
                s.x += p.x; s.y += p.y; s.z += p.z; s.w += p.w;
            }
            float4 hnv;
            hnv.x = tanhf(s.x);
            hnv.y = tanhf(s.y);
            hnv.z = tanhf(s.z);
            hnv.w = tanhf(s.w);
            *(float4*)(hnxt + b * Hn + h0) = hnv;
            *(float4*)(hrow + h0) = hnv;
            if (l == Ln - 1 && outh != nullptr)
                *(float4*)(outh + b * Hn + h0) = hnv;
            __syncthreads();

            // logits[b][l][:] = hrow @ W_o + b_o
            int v  = tid & 31;
            int kg = tid >> 5;                 // 0..7, each 128 K values
            const float* hr = hrow + kg * 128;
            const float* wo = sWo + (kg * 128) * Vn + v;
            float accv = 0.f;
#pragma unroll 8
            for (int k = 0; k < 128; ++k)
                accv = fmaf(hr[k], wo[k * Vn], accv);
            red[kg * Vn + v] = accv;
            __syncthreads();
            if (tid < Vn) {
                float sum = bo[tid];
#pragma unroll
                for (int g2 = 0; g2 < 8; ++g2) sum += red[g2 * Vn + tid];
                logits[((size_t)b * Ln + l) * Vn + tid] = sum;
            }
        }

        ++token;
        gridbar(token);

        // swap hidden buffers
        const float* t0 = hcur;
        hcur = hnxt;
        hnxt = (float*)t0;
    }
}

extern "C" void kernel_launch(void* const* d_in, const int* in_sizes, int n_in,
                              void* d_out, int out_size) {
    const int*   x      = (const int*)d_in[0];
    const float* hidden = (const float*)d_in[1];
    const float* emb    = (const float*)d_in[2];
    const float* We     = (const float*)d_in[3];
    const float* Wh     = (const float*)d_in[4];
    const float* bh     = (const float*)d_in[5];
    const float* Wo     = (const float*)d_in[6];
    const float* bo     = (const float*)d_in[7];

    float* logits = (float*)d_out;
    float* outh   = nullptr;
    if (out_size >= Bn * Ln * Vn + Bn * Hn)
        outh = logits + (size_t)Bn * Ln * Vn;

    cudaFuncSetAttribute(rnn_kernel,
                         cudaFuncAttributeMaxDynamicSharedMemorySize, SMEM_BYTES);

    precompute_P<<<Vn, Hn>>>(emb, We, bh);
    init_h<<<(Bn * Hn) / 256, 256>>>(hidden);
    rnn_kernel<<<G, NT, SMEM_BYTES>>>(x, Wh, Wo, bo, logits, outh);
}

// round 2
// speedup vs baseline: 1.0019x; 1.0019x over previous
#include <cuda_runtime.h>
#include <math.h>

#define Bn 128
#define Ln 1024
#define Vn 32
#define En 256
#define Hn 1024

#define G 128          // persistent CTAs (must all be co-resident)
#define KS 16          // K splits
#define KC 64          // K chunk = Hn/KS
#define CGn 8          // column groups
#define CT 128         // column tile = Hn/CGn
#define NT 256         // threads per CTA
#define SA_PITCH 132   // padded pitch for transposed h staging

// ---- device scratch (no allocations allowed) ----
__device__ float g_P[Vn * Hn];                 // 128 KB: embedding@W_e + b_h
__device__ float g_h[2][Bn * Hn];              // 1 MB: double-buffered hidden
__device__ float g_part[KS][Bn][Hn];           // 8 MB: split-K partials
__device__ unsigned g_arrive[G];               // barrier flags (monotonic tokens)

// smem layout (floats)
#define SW_SZ   (KC * CT)        // 8192  : W_h slice (persistent)
#define SA_SZ   (KC * SA_PITCH)  // 8448  : transposed h chunk
#define SWO_SZ  (Hn * Vn)        // 32768 : W_o (persistent)
#define HROW_SZ (Hn)             // 1024  : hnew row for logits
#define RED_SZ  (8 * Vn)         // 256   : logits reduction
#define SMEM_FLOATS (SW_SZ + SA_SZ + SWO_SZ + HROW_SZ + RED_SZ)
#define SMEM_BYTES  (SMEM_FLOATS * 4)

// ---- packed f32x2 helpers (Blackwell FFMA2 path) ----
__device__ __forceinline__ unsigned long long ffma2(unsigned long long a,
                                                    unsigned long long b,
                                                    unsigned long long c) {
    unsigned long long d;
    asm("fma.rn.f32x2 %0, %1, %2, %3;" : "=l"(d) : "l"(a), "l"(b), "l"(c));
    return d;
}
__device__ __forceinline__ unsigned long long dup2(float x) {
    unsigned long long r;
    asm("mov.b64 %0, {%1, %1};" : "=l"(r) : "f"(x));
    return r;
}
__device__ __forceinline__ void unpk2(unsigned long long v, float& lo, float& hi) {
    asm("mov.b64 {%0, %1}, %2;" : "=f"(lo), "=f"(hi) : "l"(v));
}

// ---- device-scope acquire/release for the grid barrier ----
__device__ __forceinline__ void relstore(unsigned* p, unsigned v) {
    asm volatile("st.release.gpu.u32 [%0], %1;" :: "l"(p), "r"(v) : "memory");
}
__device__ __forceinline__ unsigned acqload(const unsigned* p) {
    unsigned v;
    asm volatile("ld.acquire.gpu.u32 %0, [%1];" : "=r"(v) : "l"(p) : "memory");
    return v;
}

// Grid barrier: monotonic token, distributed flags. Safe across graph replays
// because each CTA derives its token base from its own (globally equal) slot.
__device__ __forceinline__ void gridbar(unsigned token) {
    __syncthreads();
    if (threadIdx.x == 0) relstore(&g_arrive[blockIdx.x], token);
    if (threadIdx.x < G) {
        const unsigned* p = &g_arrive[threadIdx.x];
        unsigned v = acqload(p);
        while ((int)(v - token) < 0) { __nanosleep(40); v = acqload(p); }
    }
    __syncthreads();
}

// ---- kernel A: P = embedding @ W_e + b_h ----
__global__ void precompute_P(const float* __restrict__ emb,
                             const float* __restrict__ We,
                             const float* __restrict__ bh) {
    int v = blockIdx.x;
    int h = threadIdx.x;   // 1024 threads
    float acc = bh[h];
    const float* er = emb + v * En;
#pragma unroll 8
    for (int e = 0; e < En; ++e) acc = fmaf(er[e], We[e * Hn + h], acc);
    g_P[v * Hn + h] = acc;
}

// ---- kernel B: copy initial hidden state ----
__global__ void init_h(const float* __restrict__ hidden) {
    int i = blockIdx.x * blockDim.x + threadIdx.x;
    g_h[0][i] = hidden[i];
}

// ---- kernel C: persistent RNN ----
__global__ void __launch_bounds__(NT, 1)
rnn_kernel(const int* __restrict__ x,
           const float* __restrict__ Wh,
           const float* __restrict__ Wo,
           const float* __restrict__ bo,
           float* __restrict__ logits,
           float* __restrict__ outh) {
    extern __shared__ float smem[];
    float* sW   = smem;                 // [KC][CT]
    float* sA   = sW + SW_SZ;           // [KC][SA_PITCH] transposed h chunk
    float* sWo  = sA + SA_SZ;           // [Hn][Vn]
    float* hrow = sWo + SWO_SZ;         // [Hn]
    float* red  = hrow + HROW_SZ;       // [8][Vn]

    const int tid = threadIdx.x;
    const int bid = blockIdx.x;
    const int ks  = bid >> 3;           // 0..15
    const int cg  = bid & 7;            // 0..7
    const int ty  = tid >> 4;           // 0..15 (row group of 8)
    const int tx  = tid & 15;           // 0..15 (col group of 8)

    // persistent smem loads (once per launch)
    for (int i = tid; i < SW_SZ; i += NT) {
        int k = i >> 7, j = i & 127;
        sW[i] = Wh[(ks * KC + k) * Hn + cg * CT + j];
    }
    for (int i = tid; i < SWO_SZ; i += NT) sWo[i] = Wo[i];

    unsigned token = acqload(&g_arrive[bid]);   // all slots equal at launch

    const float* hcur = g_h[0];
    float*       hnxt = g_h[1];

    for (int l = 0; l < Ln; ++l) {
        // ================= phase 1: partial GEMM h @ W_h (this K-chunk) ======
        // stage sA[k][b] = hcur[b][ks*KC + k]  (transposed, padded)
#pragma unroll
        for (int i = 0; i < (Bn * KC) / NT; ++i) {
            int idx = tid + i * NT;
            int b  = idx >> 6;
            int kk = idx & 63;
            sA[kk * SA_PITCH + b] = hcur[b * Hn + ks * KC + kk];
        }
        __syncthreads();

        unsigned long long acc[4][8];
#pragma unroll
        for (int rp = 0; rp < 4; ++rp)
#pragma unroll
            for (int c = 0; c < 8; ++c) acc[rp][c] = 0ull;

#pragma unroll 2
        for (int k = 0; k < KC; ++k) {
            const ulonglong2* ap =
                reinterpret_cast<const ulonglong2*>(sA + k * SA_PITCH + ty * 8);
            ulonglong2 a01 = ap[0];
            ulonglong2 a23 = ap[1];
            unsigned long long aa0 = a01.x, aa1 = a01.y, aa2 = a23.x, aa3 = a23.y;
            const float4* bp =
                reinterpret_cast<const float4*>(sW + k * CT + tx * 8);
            float4 bv0 = bp[0], bv1 = bp[1];
            float bw[8] = {bv0.x, bv0.y, bv0.z, bv0.w, bv1.x, bv1.y, bv1.z, bv1.w};
#pragma unroll
            for (int c = 0; c < 8; ++c) {
                unsigned long long bd = dup2(bw[c]);
                acc[0][c] = ffma2(aa0, bd, acc[0][c]);
                acc[1][c] = ffma2(aa1, bd, acc[1][c]);
                acc[2][c] = ffma2(aa2, bd, acc[2][c]);
                acc[3][c] = ffma2(aa3, bd, acc[3][c]);
            }
        }

        // write partials: rows ty*8 + rp*2 (+1), cols cg*CT + tx*8 .. +8
        {
            int r0 = ty * 8;
            int jc = cg * CT + tx * 8;
#pragma unroll
            for (int rp = 0; rp < 4; ++rp) {
                float lo[8], hi[8];
#pragma unroll
                for (int c = 0; c < 8; ++c) unpk2(acc[rp][c], lo[c], hi[c]);
                float* d0 = &g_part[ks][r0 + rp * 2][jc];
                float* d1 = &g_part[ks][r0 + rp * 2 + 1][jc];
                ((float4*)d0)[0] = make_float4(lo[0], lo[1], lo[2], lo[3]);
                ((float4*)d0)[1] = make_float4(lo[4], lo[5], lo[6], lo[7]);
                ((float4*)d1)[0] = make_float4(hi[0], hi[1], hi[2], hi[3]);
                ((float4*)d1)[1] = make_float4(hi[4], hi[5], hi[6], hi[7]);
            }
        }

        ++token;
        gridbar(token);

        // ================= phase 2: reduce + tanh + logits (row b = bid) =====
        {
            const int b  = bid;
            const int xv = x[b * Ln + l];
            const float* Prow = g_P + xv * Hn;
            const int h0 = tid * 4;

            float4 s = *(const float4*)(Prow + h0);
#pragma unroll
            for (int ksi = 0; ksi < KS; ++ksi) {
                float4 p = *(const float4*)(&g_part[ksi][b][h0]);
                s.x += p.x; s.y += p.y; s.z += p.z; s.w += p.w;
            }
            float4 hnv;
            hnv.x = tanhf(s.x);
            hnv.y = tanhf(s.y);
            hnv.z = tanhf(s.z);
            hnv.w = tanhf(s.w);
            *(float4*)(hnxt + b * Hn + h0) = hnv;
            *(float4*)(hrow + h0) = hnv;
            if (l == Ln - 1 && outh != nullptr)
                *(float4*)(outh + b * Hn + h0) = hnv;
            __syncthreads();

            // logits[b][l][:] = hrow @ W_o + b_o
            int v  = tid & 31;
            int kg = tid >> 5;                 // 0..7, each 128 K values
            const float* hr = hrow + kg * 128;
            const float* wo = sWo + (kg * 128) * Vn + v;
            float accv = 0.f;
#pragma unroll 8
            for (int k = 0; k < 128; ++k)
                accv = fmaf(hr[k], wo[k * Vn], accv);
            red[kg * Vn + v] = accv;
            __syncthreads();
            if (tid < Vn) {
                float sum = bo[tid];
#pragma unroll
                for (int g2 = 0; g2 < 8; ++g2) sum += red[g2 * Vn + tid];
                logits[((size_t)b * Ln + l) * Vn + tid] = sum;
            }
        }

        ++token;
        gridbar(token);

        // swap hidden buffers
        const float* t0 = hcur;
        hcur = hnxt;
        hnxt = (float*)t0;
    }
}

extern "C" void kernel_launch(void* const* d_in, const int* in_sizes, int n_in,
                              void* d_out, int out_size) {
    const int*   x      = (const int*)d_in[0];
    const float* hidden = (const float*)d_in[1];
    const float* emb    = (const float*)d_in[2];
    const float* We     = (const float*)d_in[3];
    const float* Wh     = (const float*)d_in[4];
    const float* bh     = (const float*)d_in[5];
    const float* Wo     = (const float*)d_in[6];
    const float* bo     = (const float*)d_in[7];

    float* logits = (float*)d_out;
    float* outh   = nullptr;
    if (out_size >= Bn * Ln * Vn + Bn * Hn)
        outh = logits + (size_t)Bn * Ln * Vn;

    cudaFuncSetAttribute(rnn_kernel,
                         cudaFuncAttributeMaxDynamicSharedMemorySize, SMEM_BYTES);

    precompute_P<<<Vn, Hn>>>(emb, We, bh);
    init_h<<<(Bn * Hn) / 256, 256>>>(hidden);
    rnn_kernel<<<G, NT, SMEM_BYTES>>>(x, Wh, Wo, bo, logits, outh);
}

// round 4
// speedup vs baseline: 1.3588x; 1.3562x over previous
#include <cuda_runtime.h>
#include <cuda_bf16.h>
#include <stdint.h>
#include <math.h>

#define Bn 128
#define Ln 1024
#define Vn 32
#define En 256
#define Hn 1024
#define NTOT 1056            // Hn + Vn (W_o folded in)

#define KSP 4                // K splits
#define KSL 256              // K per CTA
#define NTL 33               // N tiles (32 Wh + 1 Wo)
#define NSL 32               // N cols per CTA
#define G   (KSP * NTL)      // 132 persistent CTAs
#define NT  256
#define PK  264              // padded smem k-pitch (bf16 elems) -> conflict-free frags

// ---------------- device scratch ----------------
__device__ float         g_P[Vn * Hn];
__device__ __nv_bfloat16 g_hbf_hi[2][Bn * Hn];
__device__ __nv_bfloat16 g_hbf_lo[2][Bn * Hn];
__device__ __nv_bfloat16 g_WT_hi[NTOT * Hn];   // [n][k]: n<1024 WhT, n>=1024 WoT
__device__ __nv_bfloat16 g_WT_lo[NTOT * Hn];
__device__ float         g_part[KSP][Bn][NTOT];
__device__ unsigned      g_arrive[G];

// smem: sAhi[128][PK], sAlo[128][PK], sBhi[32][PK], sBlo[32][PK]  (bf16)
#define SMEM_BYTES ((128 * PK * 2 + 32 * PK * 2) * 2)   // 168960

// ---------------- helpers ----------------
#define MMA16816(d, a0, a1, a2, a3, b0, b1) \
    asm volatile("mma.sync.aligned.m16n8k16.row.col.f32.bf16.bf16.f32 " \
        "{%0,%1,%2,%3}, {%4,%5,%6,%7}, {%8,%9}, {%0,%1,%2,%3};" \
        : "+f"((d)[0]), "+f"((d)[1]), "+f"((d)[2]), "+f"((d)[3]) \
        : "r"(a0), "r"(a1), "r"(a2), "r"(a3), "r"(b0), "r"(b1))

__device__ __forceinline__ void relstore(unsigned* p, unsigned v) {
    asm volatile("st.release.gpu.u32 [%0], %1;" :: "l"(p), "r"(v) : "memory");
}
__device__ __forceinline__ unsigned acqload(const unsigned* p) {
    unsigned v;
    asm volatile("ld.acquire.gpu.u32 %0, [%1];" : "=r"(v) : "l"(p) : "memory");
    return v;
}
__device__ __forceinline__ void gridbar(unsigned token) {
    __syncthreads();
    if (threadIdx.x == 0) {
        asm volatile("fence.acq_rel.gpu;" ::: "memory");
        relstore(&g_arrive[blockIdx.x], token);
    }
    if (threadIdx.x < G) {
        const unsigned* p = &g_arrive[threadIdx.x];
        unsigned v = acqload(p);
        while ((int)(v - token) < 0) { __nanosleep(32); v = acqload(p); }
    }
    __syncthreads();
}
__device__ __forceinline__ void pack_hilo(float v, unsigned short& hi, unsigned short& lo) {
    __nv_bfloat16 hb = __float2bfloat16(v);
    hi = __bfloat16_as_ushort(hb);
    lo = __bfloat16_as_ushort(__float2bfloat16(v - __bfloat162float(hb)));
}

// ---------------- the single persistent kernel ----------------
__global__ void __launch_bounds__(NT, 1)
rnn_all(const int* __restrict__ x, const float* __restrict__ hidden,
        const float* __restrict__ emb, const float* __restrict__ We,
        const float* __restrict__ Wh, const float* __restrict__ bh,
        const float* __restrict__ Wo, const float* __restrict__ bo,
        float* __restrict__ logits, float* __restrict__ outh) {
    extern __shared__ __align__(16) char dsm[];
    __nv_bfloat16* sAhi = (__nv_bfloat16*)dsm;
    __nv_bfloat16* sAlo = sAhi + 128 * PK;
    __nv_bfloat16* sBhi = sAlo + 128 * PK;
    __nv_bfloat16* sBlo = sBhi + 32 * PK;

    const int tid = threadIdx.x, bid = blockIdx.x;
    const int kt  = bid / NTL;          // 0..3
    const int ntl = bid % NTL;          // 0..32
    const int lane = tid & 31, w = tid >> 5;
    const int gq = lane >> 2, tg = lane & 3;
    const int m0 = w * 16;

    unsigned token = acqload(&g_arrive[bid]);

    // ======== prologue ========
    // W^T hi/lo split: CTA owns n rows [bid*8, bid*8+8); n<1024 -> Wh, else Wo
    for (int k2 = tid; k2 < Hn; k2 += NT) {
#pragma unroll
        for (int j = 0; j < 8; ++j) {
            int n = bid * 8 + j;
            float wv = (n < Hn) ? Wh[k2 * Hn + n] : Wo[k2 * Vn + (n - Hn)];
            unsigned short hi, lo; pack_hilo(wv, hi, lo);
            g_WT_hi[n * Hn + k2] = __ushort_as_bfloat16(hi);
            g_WT_lo[n * Hn + k2] = __ushort_as_bfloat16(lo);
        }
    }
    // P = embedding @ W_e + b_h  (one element per thread; bid<128 covers it)
    {
        int e = bid * NT + tid;
        if (e < Vn * Hn) {
            int v = e >> 10, h = e & 1023;
            float acc = bh[h];
            const float* er = emb + v * En;
#pragma unroll 8
            for (int q = 0; q < En; ++q) acc = fmaf(er[q], We[q * Hn + h], acc);
            g_P[e] = acc;
        }
    }
    // h0 -> bf16 hi/lo buffer 0
    if (bid < Bn) {
        int i0 = bid * Hn + tid * 4;
        float4 hv = *(const float4*)(hidden + i0);
        float vv[4] = {hv.x, hv.y, hv.z, hv.w};
        unsigned short uh[4], ul[4];
#pragma unroll
        for (int j = 0; j < 4; ++j) pack_hilo(vv[j], uh[j], ul[j]);
        *(uint2*)(&g_hbf_hi[0][i0]) =
            make_uint2(uh[0] | (uh[1] << 16), uh[2] | (uh[3] << 16));
        *(uint2*)(&g_hbf_lo[0][i0]) =
            make_uint2(ul[0] | (ul[1] << 16), ul[2] | (ul[3] << 16));
    }
    gridbar(++token);

    // persistent B tile -> smem (reads other CTAs' g_WT after barrier)
    for (int idx = tid; idx < NSL * KSL; idx += NT) {
        int n = idx >> 8, k = idx & 255;
        int src = (ntl * NSL + n) * Hn + kt * KSL + k;
        sBhi[n * PK + k] = g_WT_hi[src];
        sBlo[n * PK + k] = g_WT_lo[src];
    }
    __syncthreads();

    // ======== recurrence: l = 0..Ln (iter l consumes h_l, makes h_{l+1} & logits[l-1]) ====
    for (int l = 0; l <= Ln; ++l) {
        const int c = l & 1;

        // ---- stage A slice (h_l hi/lo rows 0..127, k in [kt*256, +256)) ----
#pragma unroll
        for (int it = 0; it < 16; ++it) {
            int i = (it * NT + tid) * 8;
            int row = i >> 8, k = i & 255;
            *(uint4*)(sAhi + row * PK + k) =
                *(const uint4*)(&g_hbf_hi[c][row * Hn + kt * KSL + k]);
            *(uint4*)(sAlo + row * PK + k) =
                *(const uint4*)(&g_hbf_lo[c][row * Hn + kt * KSL + k]);
        }
        __syncthreads();

        // ---- MMA: C[16 rows x 32 cols] per warp, K=256, 3 bf16 terms ----
        float acc[4][4];
#pragma unroll
        for (int nt = 0; nt < 4; ++nt)
#pragma unroll
            for (int q = 0; q < 4; ++q) acc[nt][q] = 0.f;

        const __nv_bfloat16* paH = sAhi + (m0 + gq) * PK + tg * 2;
        const __nv_bfloat16* paL = sAlo + (m0 + gq) * PK + tg * 2;
#pragma unroll 4
        for (int kk = 0; kk < 16; ++kk) {
            const int ko = kk * 16;
            uint32_t ah0 = *(const uint32_t*)(paH + ko);
            uint32_t ah1 = *(const uint32_t*)(paH + ko + 8 * PK);
            uint32_t ah2 = *(const uint32_t*)(paH + ko + 8);
            uint32_t ah3 = *(const uint32_t*)(paH + ko + 8 * PK + 8);
            uint32_t al0 = *(const uint32_t*)(paL + ko);
            uint32_t al1 = *(const uint32_t*)(paL + ko + 8 * PK);
            uint32_t al2 = *(const uint32_t*)(paL + ko + 8);
            uint32_t al3 = *(const uint32_t*)(paL + ko + 8 * PK + 8);
#pragma unroll
            for (int nt = 0; nt < 4; ++nt) {
                const __nv_bfloat16* pb = sBhi + (nt * 8 + gq) * PK + ko + tg * 2;
                const __nv_bfloat16* pl = sBlo + (nt * 8 + gq) * PK + ko + tg * 2;
                uint32_t bh0 = *(const uint32_t*)(pb);
                uint32_t bh1 = *(const uint32_t*)(pb + 8);
                uint32_t bl0 = *(const uint32_t*)(pl);
                uint32_t bl1 = *(const uint32_t*)(pl + 8);
                MMA16816(acc[nt], ah0, ah1, ah2, ah3, bh0, bh1);
                MMA16816(acc[nt], ah0, ah1, ah2, ah3, bl0, bl1);
                MMA16816(acc[nt], al0, al1, al2, al3, bh0, bh1);
            }
        }

        // ---- write partials ----
#pragma unroll
        for (int nt = 0; nt < 4; ++nt) {
            int col = ntl * NSL + nt * 8 + tg * 2;
            float* p0 = &g_part[kt][m0 + gq][col];
            float* p1 = &g_part[kt][m0 + gq + 8][col];
            *(float2*)p0 = make_float2(acc[nt][0], acc[nt][1]);
            *(float2*)p1 = make_float2(acc[nt][2], acc[nt][3]);
        }
        gridbar(++token);

        // ---- phase 2: reduce + tanh + pack (row b = bid), logits[l-1] ----
        if (bid < Bn) {
            const int b = bid;
            if (l < Ln) {
                const int xv = x[b * Ln + l];
                const int h0 = tid * 4;
                float4 s = *(const float4*)(g_P + xv * Hn + h0);
#pragma unroll
                for (int j = 0; j < KSP; ++j) {
                    float4 p = *(const float4*)(&g_part[j][b][h0]);
                    s.x += p.x; s.y += p.y; s.z += p.z; s.w += p.w;
                }
                float4 hv;
                hv.x = tanhf(s.x); hv.y = tanhf(s.y);
                hv.z = tanhf(s.z); hv.w = tanhf(s.w);
                float vv[4] = {hv.x, hv.y, hv.z, hv.w};
                unsigned short uh[4], ul[4];
#pragma unroll
                for (int j = 0; j < 4; ++j) pack_hilo(vv[j], uh[j], ul[j]);
                int i0 = b * Hn + h0;
                *(uint2*)(&g_hbf_hi[1 - c][i0]) =
                    make_uint2(uh[0] | (uh[1] << 16), uh[2] | (uh[3] << 16));
                *(uint2*)(&g_hbf_lo[1 - c][i0]) =
                    make_uint2(ul[0] | (ul[1] << 16), ul[2] | (ul[3] << 16));
                if (l == Ln - 1)
                    *(float4*)(outh + i0) = hv;
            }
            if (l > 0 && tid < Vn) {
                float s = bo[tid];
#pragma unroll
                for (int j = 0; j < KSP; ++j) s += g_part[j][b][Hn + tid];
                logits[((size_t)b * Ln + (l - 1)) * Vn + tid] = s;
            }
        }
        if (l < Ln) gridbar(++token);
    }
}

extern "C" void kernel_launch(void* const* d_in, const int* in_sizes, int n_in,
                              void* d_out, int out_size) {
    const int*   x      = (const int*)d_in[0];
    const float* hidden = (const float*)d_in[1];
    const float* emb    = (const float*)d_in[2];
    const float* We     = (const float*)d_in[3];
    const float* Wh     = (const float*)d_in[4];
    const float* bh     = (const float*)d_in[5];
    const float* Wo     = (const float*)d_in[6];
    const float* bo     = (const float*)d_in[7];

    float* logits = (float*)d_out;
    float* outh   = logits + (size_t)Bn * Ln * Vn;

    cudaFuncSetAttribute(rnn_all,
                         cudaFuncAttributeMaxDynamicSharedMemorySize, SMEM_BYTES);
    rnn_all<<<G, NT, SMEM_BYTES>>>(x, hidden, emb, We, Wh, bh, Wo, bo, logits, outh);
}

// round 6
// speedup vs baseline: 1.5686x; 1.1544x over previous
#include <cuda_runtime.h>
#include <cuda_bf16.h>
#include <stdint.h>
#include <math.h>

#define Bn 128
#define Ln 1024
#define Vn 32
#define En 256
#define Hn 1024
#define NTOT 1056            // Hn + Vn (W_o folded)
#define NPAD 1088            // padded to 17*64

#define KSP 8                // K splits
#define KSL 128              // K per CTA
#define NTL 17               // N tiles
#define NSL 64               // N cols per CTA
#define G   (KSP * NTL)      // 136 persistent CTAs
#define NT  512
#define PK  136              // smem k-pitch (bf16 elems); 272B row stride -> LDSM conflict-free

// ---------------- device scratch ----------------
__device__ float         g_P[Vn * Hn];
__device__ __nv_bfloat16 g_hbf_hi[2][Bn * Hn];
__device__ __nv_bfloat16 g_hbf_lo[2][Bn * Hn];
__device__ __nv_bfloat16 g_WT_hi[NPAD * Hn];   // [n][k]; n<1024 WhT, 1024..1055 WoT, rest 0
__device__ __nv_bfloat16 g_WT_lo[NPAD * Hn];
__device__ float         g_part[KSP][Bn][NPAD];
__device__ unsigned      g_arrive[G];

// smem: sAhi[128][PK], sAlo[128][PK], sBhi[64][PK], sBlo[64][PK] (bf16) = 104448 B
#define SMEM_BYTES ((128 * PK * 2 + 64 * PK * 2) * 2)

// ---------------- helpers ----------------
#define MMA16816(d, a0, a1, a2, a3, b0, b1) \
    asm volatile("mma.sync.aligned.m16n8k16.row.col.f32.bf16.bf16.f32 " \
        "{%0,%1,%2,%3}, {%4,%5,%6,%7}, {%8,%9}, {%0,%1,%2,%3};" \
        : "+f"((d)[0]), "+f"((d)[1]), "+f"((d)[2]), "+f"((d)[3]) \
        : "r"(a0), "r"(a1), "r"(a2), "r"(a3), "r"(b0), "r"(b1))

#define LDSM4(r0, r1, r2, r3, addr) \
    asm volatile("ldmatrix.sync.aligned.m8n8.x4.shared.b16 {%0,%1,%2,%3}, [%4];" \
        : "=r"(r0), "=r"(r1), "=r"(r2), "=r"(r3) : "r"(addr))

__device__ __forceinline__ uint32_t smem_u32(const void* p) {
    uint32_t a;
    asm("{ .reg .u64 t; cvta.to.shared.u64 t, %1; cvt.u32.u64 %0, t; }"
        : "=r"(a) : "l"(p));
    return a;
}
__device__ __forceinline__ void relstore(unsigned* p, unsigned v) {
    asm volatile("st.release.gpu.u32 [%0], %1;" :: "l"(p), "r"(v) : "memory");
}
__device__ __forceinline__ unsigned acqload(const unsigned* p) {
    unsigned v;
    asm volatile("ld.acquire.gpu.u32 %0, [%1];" : "=r"(v) : "l"(p) : "memory");
    return v;
}
__device__ __forceinline__ void gridbar(unsigned token) {
    __syncthreads();
    if (threadIdx.x == 0) {
        asm volatile("fence.acq_rel.gpu;" ::: "memory");
        relstore(&g_arrive[blockIdx.x], token);
    }
    if (threadIdx.x < G) {
        const unsigned* p = &g_arrive[threadIdx.x];
        unsigned v = acqload(p);
        while ((int)(v - token) < 0) { __nanosleep(32); v = acqload(p); }
    }
    __syncthreads();
}
__device__ __forceinline__ void pack_hilo(float v, unsigned short& hi, unsigned short& lo) {
    __nv_bfloat16 hb = __float2bfloat16(v);
    hi = __bfloat16_as_ushort(hb);
    lo = __bfloat16_as_ushort(__float2bfloat16(v - __bfloat162float(hb)));
}

// ---------------- the single persistent kernel ----------------
__global__ void __launch_bounds__(NT, 1)
rnn_all(const int* __restrict__ x, const float* __restrict__ hidden,
        const float* __restrict__ emb, const float* __restrict__ We,
        const float* __restrict__ Wh, const float* __restrict__ bh,
        const float* __restrict__ Wo, const float* __restrict__ bo,
        float* __restrict__ logits, float* __restrict__ outh) {
    extern __shared__ __align__(16) char dsm[];
    __nv_bfloat16* sAhi = (__nv_bfloat16*)dsm;
    __nv_bfloat16* sAlo = sAhi + 128 * PK;
    __nv_bfloat16* sBhi = sAlo + 128 * PK;
    __nv_bfloat16* sBlo = sBhi + 64 * PK;

    const int tid = threadIdx.x, bid = blockIdx.x;
    const int kt  = bid / NTL;          // 0..7
    const int ntl = bid % NTL;          // 0..16
    const int lane = tid & 31, w = tid >> 5;     // 16 warps
    const int gq = lane >> 2, tg = lane & 3;
    const int m0 = (w >> 1) * 16;       // 8 m-groups of 16 rows
    const int nh = w & 1;               // n-half: 32 cols each

    unsigned token = acqload(&g_arrive[bid]);

    // ======== prologue ========
    // W^T hi/lo split: CTA owns n in [bid*8, bid*8+8); pad region -> 0
    for (int k2 = tid; k2 < Hn; k2 += NT) {
#pragma unroll
        for (int j = 0; j < 8; ++j) {
            int n = bid * 8 + j;
            float wv = 0.f;
            if (n < Hn)            wv = Wh[k2 * Hn + n];
            else if (n < NTOT)     wv = Wo[k2 * Vn + (n - Hn)];
            unsigned short hi, lo; pack_hilo(wv, hi, lo);
            g_WT_hi[n * Hn + k2] = __ushort_as_bfloat16(hi);
            g_WT_lo[n * Hn + k2] = __ushort_as_bfloat16(lo);
        }
    }
    // P = embedding @ W_e + b_h
    {
        int e = bid * NT + tid;
        if (e < Vn * Hn) {
            int v = e >> 10, h = e & 1023;
            float acc = bh[h];
            const float* er = emb + v * En;
#pragma unroll 8
            for (int q = 0; q < En; ++q) acc = fmaf(er[q], We[q * Hn + h], acc);
            g_P[e] = acc;
        }
    }
    // h0 -> bf16 hi/lo buffer 0
    if (bid < Bn) {
        int i0 = bid * Hn + tid * 2;
        float2 hv = *(const float2*)(hidden + i0);
        unsigned short h0u, l0u, h1u, l1u;
        pack_hilo(hv.x, h0u, l0u); pack_hilo(hv.y, h1u, l1u);
        *(uint32_t*)(&g_hbf_hi[0][i0]) = (uint32_t)h0u | ((uint32_t)h1u << 16);
        *(uint32_t*)(&g_hbf_lo[0][i0]) = (uint32_t)l0u | ((uint32_t)l1u << 16);
    }
    gridbar(++token);

    // persistent B tile -> smem: rows n 0..63 (global ntl*64+n), k 0..127
    for (int idx = tid; idx < NSL * KSL; idx += NT) {
        int n = idx >> 7, k = idx & 127;
        int src = (ntl * NSL + n) * Hn + kt * KSL + k;
        sBhi[n * PK + k] = g_WT_hi[src];
        sBlo[n * PK + k] = g_WT_lo[src];
    }
    __syncthreads();

    // fragment base addresses (bytes, shared space)
    const uint32_t aBaseHi = smem_u32(sAhi) +
        (uint32_t)(((m0 + (lane & 7) + ((lane >> 3) & 1) * 8) * PK + (lane >> 4) * 8) * 2);
    const uint32_t aBaseLo = aBaseHi + (uint32_t)(128 * PK * 2);
    const int nl0 = (nh * 4 + 0 + (lane >> 4)) * 8 + (lane & 7);
    const int nl1 = (nh * 4 + 2 + (lane >> 4)) * 8 + (lane & 7);
    const int bko = ((lane >> 3) & 1) * 8;
    const uint32_t bBaseHi0 = smem_u32(sBhi) + (uint32_t)((nl0 * PK + bko) * 2);
    const uint32_t bBaseHi1 = smem_u32(sBhi) + (uint32_t)((nl1 * PK + bko) * 2);
    const uint32_t bBaseLo0 = bBaseHi0 + (uint32_t)(64 * PK * 2);
    const uint32_t bBaseLo1 = bBaseHi1 + (uint32_t)(64 * PK * 2);

    // ======== recurrence: iter l consumes h_l -> partials(h_{l+1}, logits_l) ========
    for (int l = 0; l <= Ln; ++l) {
        const int c = l & 1;
        const bool doMMA = (l < Ln) || (ntl == NTL - 1);

        if (doMMA) {   // stage A slice: h_l hi/lo rows 0..127, k in [kt*128,+128)
#pragma unroll
            for (int it = 0; it < 4; ++it) {
                int i = (it * NT + tid) * 8;
                int row = i >> 7, k = i & 127;
                *(uint4*)(sAhi + row * PK + k) =
                    *(const uint4*)(&g_hbf_hi[c][row * Hn + kt * KSL + k]);
                *(uint4*)(sAlo + row * PK + k) =
                    *(const uint4*)(&g_hbf_lo[c][row * Hn + kt * KSL + k]);
            }
        }
        __syncthreads();

        if (doMMA) {
            float acc[4][4];
#pragma unroll
            for (int nt = 0; nt < 4; ++nt)
#pragma unroll
                for (int q = 0; q < 4; ++q) acc[nt][q] = 0.f;

#pragma unroll
            for (int kk = 0; kk < 8; ++kk) {
                const uint32_t ko = kk * 32;
                uint32_t ah0, ah1, ah2, ah3, al0, al1, al2, al3;
                LDSM4(ah0, ah1, ah2, ah3, aBaseHi + ko);
                LDSM4(al0, al1, al2, al3, aBaseLo + ko);
                uint32_t b00, b01, b10, b11, b20, b21, b30, b31;
                LDSM4(b00, b01, b10, b11, bBaseHi0 + ko);   // hi: nt0, nt1
                LDSM4(b20, b21, b30, b31, bBaseHi1 + ko);   // hi: nt2, nt3
                uint32_t c00, c01, c10, c11, c20, c21, c30, c31;
                LDSM4(c00, c01, c10, c11, bBaseLo0 + ko);   // lo: nt0, nt1
                LDSM4(c20, c21, c30, c31, bBaseLo1 + ko);   // lo: nt2, nt3

                MMA16816(acc[0], ah0, ah1, ah2, ah3, b00, b01);
                MMA16816(acc[1], ah0, ah1, ah2, ah3, b10, b11);
                MMA16816(acc[2], ah0, ah1, ah2, ah3, b20, b21);
                MMA16816(acc[3], ah0, ah1, ah2, ah3, b30, b31);
                MMA16816(acc[0], ah0, ah1, ah2, ah3, c00, c01);
                MMA16816(acc[1], ah0, ah1, ah2, ah3, c10, c11);
                MMA16816(acc[2], ah0, ah1, ah2, ah3, c20, c21);
                MMA16816(acc[3], ah0, ah1, ah2, ah3, c30, c31);
                MMA16816(acc[0], al0, al1, al2, al3, b00, b01);
                MMA16816(acc[1], al0, al1, al2, al3, b10, b11);
                MMA16816(acc[2], al0, al1, al2, al3, b20, b21);
                MMA16816(acc[3], al0, al1, al2, al3, b30, b31);
            }

            // write partials
#pragma unroll
            for (int nt = 0; nt < 4; ++nt) {
                int col = ntl * NSL + (nh * 4 + nt) * 8 + tg * 2;
                *(float2*)(&g_part[kt][m0 + gq][col])     = make_float2(acc[nt][0], acc[nt][1]);
                *(float2*)(&g_part[kt][m0 + gq + 8][col]) = make_float2(acc[nt][2], acc[nt][3]);
            }
        }
        gridbar(++token);

        // ---- phase 2: reduce + tanh + pack (row b = bid), logits[l-1] ----
        if (bid < Bn) {
            const int b = bid;
            if (l < Ln) {
                const int xv = x[b * Ln + l];
                const int h0 = tid * 2;
                float2 s = *(const float2*)(g_P + xv * Hn + h0);
#pragma unroll
                for (int j = 0; j < KSP; ++j) {
                    float2 p = *(const float2*)(&g_part[j][b][h0]);
                    s.x += p.x; s.y += p.y;
                }
                float2 hv;
                hv.x = tanhf(s.x); hv.y = tanhf(s.y);
                unsigned short h0u, l0u, h1u, l1u;
                pack_hilo(hv.x, h0u, l0u); pack_hilo(hv.y, h1u, l1u);
                int i0 = b * Hn + h0;
                *(uint32_t*)(&g_hbf_hi[1 - c][i0]) = (uint32_t)h0u | ((uint32_t)h1u << 16);
                *(uint32_t*)(&g_hbf_lo[1 - c][i0]) = (uint32_t)l0u | ((uint32_t)l1u << 16);
                if (l == Ln - 1)
                    *(float2*)(outh + i0) = hv;
            }
            if (l > 0 && tid < Vn) {
                float s = bo[tid];
#pragma unroll
                for (int j = 0; j < KSP; ++j) s += g_part[j][b][Hn + tid];
                logits[((size_t)b * Ln + (l - 1)) * Vn + tid] = s;
            }
        }
        if (l < Ln) gridbar(++token);
    }
}

extern "C" void kernel_launch(void* const* d_in, const int* in_sizes, int n_in,
                              void* d_out, int out_size) {
    const int*   x      = (const int*)d_in[0];
    const float* hidden = (const float*)d_in[1];
    const float* emb    = (const float*)d_in[2];
    const float* We     = (const float*)d_in[3];
    const float* Wh     = (const float*)d_in[4];
    const float* bh     = (const float*)d_in[5];
    const float* Wo     = (const float*)d_in[6];
    const float* bo     = (const float*)d_in[7];

    float* logits = (float*)d_out;
    float* outh   = logits + (size_t)Bn * Ln * Vn;

    cudaFuncSetAttribute(rnn_all,
                         cudaFuncAttributeMaxDynamicSharedMemorySize, SMEM_BYTES);
    rnn_all<<<G, NT, SMEM_BYTES>>>(x, hidden, emb, We, Wh, bh, Wo, bo, logits, outh);
}

// round 7
// speedup vs baseline: 2.7568x; 1.7574x over previous
#include <cuda_runtime.h>
#include <cuda_bf16.h>
#include <stdint.h>
#include <math.h>

#define Bn 128
#define Ln 1024
#define Vn 32
#define En 256
#define Hn 1024
#define NTOT 1056            // Hn + Vn (W_o folded)
#define NPAD 1088            // padded to 17*64

#define KSP 8                // K splits
#define KSL 128              // K per CTA
#define NTL 17               // N tiles
#define NSL 64               // N cols per CTA
#define G   (KSP * NTL)      // 136 persistent CTAs
#define NT  512
#define PK  136              // smem k-pitch (bf16); 272B row stride -> LDSM conflict-free

// ---------------- device scratch ----------------
__device__ float         g_P[Vn * Hn];
__device__ __nv_bfloat16 g_hbf_hi[2][Bn * Hn];
__device__ __nv_bfloat16 g_hbf_lo[2][Bn * Hn];
__device__ __nv_bfloat16 g_WT_hi[NPAD * Hn];   // [n][k]; n<1024 WhT, 1024..1055 WoT, rest 0
__device__ __nv_bfloat16 g_WT_lo[NPAD * Hn];
__device__ float         g_part[KSP][Bn][NPAD];
__device__ unsigned      g_cnt1;               // barrier-1: signaled by all G
__device__ unsigned      g_cnt2;               // barrier-2: signaled by Bn producers

// smem: sAhi[128][PK], sAlo[128][PK], sBhi[64][PK], sBlo[64][PK] (bf16) = 104448 B
#define SMEM_BYTES ((128 * PK * 2 + 64 * PK * 2) * 2)

// ---------------- helpers ----------------
#define MMA16816(d, a0, a1, a2, a3, b0, b1) \
    asm volatile("mma.sync.aligned.m16n8k16.row.col.f32.bf16.bf16.f32 " \
        "{%0,%1,%2,%3}, {%4,%5,%6,%7}, {%8,%9}, {%0,%1,%2,%3};" \
        : "+f"((d)[0]), "+f"((d)[1]), "+f"((d)[2]), "+f"((d)[3]) \
        : "r"(a0), "r"(a1), "r"(a2), "r"(a3), "r"(b0), "r"(b1))

#define LDSM4(r0, r1, r2, r3, addr) \
    asm volatile("ldmatrix.sync.aligned.m8n8.x4.shared.b16 {%0,%1,%2,%3}, [%4];" \
        : "=r"(r0), "=r"(r1), "=r"(r2), "=r"(r3) : "r"(addr))

__device__ __forceinline__ uint32_t smem_u32(const void* p) {
    uint32_t a;
    asm("{ .reg .u64 t; cvta.to.shared.u64 t, %1; cvt.u32.u64 %0, t; }"
        : "=r"(a) : "l"(p));
    return a;
}
__device__ __forceinline__ unsigned acqload(const unsigned* p) {
    unsigned v;
    asm volatile("ld.acquire.gpu.u32 %0, [%1];" : "=r"(v) : "l"(p) : "memory");
    return v;
}
__device__ __forceinline__ void arrive(unsigned* cnt) {
    asm volatile("red.release.gpu.global.add.u32 [%0], 1;" :: "l"(cnt) : "memory");
}
__device__ __forceinline__ void waitcnt(unsigned* cnt, unsigned target) {
    unsigned v = acqload(cnt);
    while ((int)(v - target) < 0) v = acqload(cnt);
}
__device__ __forceinline__ uint4 ldcg4(const void* p) {
    uint4 r;
    asm volatile("ld.global.cg.v4.u32 {%0,%1,%2,%3}, [%4];"
        : "=r"(r.x), "=r"(r.y), "=r"(r.z), "=r"(r.w) : "l"(p));
    return r;
}
__device__ __forceinline__ float2 ldcg2f(const void* p) {
    float2 r;
    asm volatile("ld.global.cg.v2.f32 {%0,%1}, [%2];"
        : "=f"(r.x), "=f"(r.y) : "l"(p));
    return r;
}
__device__ __forceinline__ float ldcgf(const void* p) {
    float r;
    asm volatile("ld.global.cg.f32 %0, [%1];" : "=f"(r) : "l"(p));
    return r;
}
__device__ __forceinline__ void pack_hilo(float v, unsigned short& hi, unsigned short& lo) {
    __nv_bfloat16 hb = __float2bfloat16(v);
    hi = __bfloat16_as_ushort(hb);
    lo = __bfloat16_as_ushort(__float2bfloat16(v - __bfloat162float(hb)));
}

// ---------------- the single persistent kernel ----------------
__global__ void __launch_bounds__(NT, 1)
rnn_all(const int* __restrict__ x, const float* __restrict__ hidden,
        const float* __restrict__ emb, const float* __restrict__ We,
        const float* __restrict__ Wh, const float* __restrict__ bh,
        const float* __restrict__ Wo, const float* __restrict__ bo,
        float* __restrict__ logits, float* __restrict__ outh) {
    extern __shared__ __align__(16) char dsm[];
    __nv_bfloat16* sAhi = (__nv_bfloat16*)dsm;
    __nv_bfloat16* sAlo = sAhi + 128 * PK;
    __nv_bfloat16* sBhi = sAlo + 128 * PK;
    __nv_bfloat16* sBlo = sBhi + 64 * PK;

    const int tid = threadIdx.x, bid = blockIdx.x;
    const int kt  = bid / NTL;          // 0..7
    const int ntl = bid % NTL;          // 0..16
    const int lane = tid & 31, w = tid >> 5;     // 16 warps
    const int gq = lane >> 2, tg = lane & 3;
    const int m0 = (w >> 1) * 16;       // 8 m-groups of 16 rows
    const int nh = w & 1;               // n-half: 32 cols each

    // barrier bases (quiescent at launch; counters are monotonic across replays)
    unsigned t1 = acqload(&g_cnt1);
    unsigned t2 = acqload(&g_cnt2);

    // ======== prologue ========
    for (int k2 = tid; k2 < Hn; k2 += NT) {
#pragma unroll
        for (int j = 0; j < 8; ++j) {
            int n = bid * 8 + j;
            float wv = 0.f;
            if (n < Hn)            wv = Wh[k2 * Hn + n];
            else if (n < NTOT)     wv = Wo[k2 * Vn + (n - Hn)];
            unsigned short hi, lo; pack_hilo(wv, hi, lo);
            g_WT_hi[n * Hn + k2] = __ushort_as_bfloat16(hi);
            g_WT_lo[n * Hn + k2] = __ushort_as_bfloat16(lo);
        }
    }
    {
        int e = bid * NT + tid;
        if (e < Vn * Hn) {
            int v = e >> 10, h = e & 1023;
            float acc = bh[h];
            const float* er = emb + v * En;
#pragma unroll 8
            for (int q = 0; q < En; ++q) acc = fmaf(er[q], We[q * Hn + h], acc);
            g_P[e] = acc;
        }
    }
    if (bid < Bn) {
        int i0 = bid * Hn + tid * 2;
        float2 hv = *(const float2*)(hidden + i0);
        unsigned short h0u, l0u, h1u, l1u;
        pack_hilo(hv.x, h0u, l0u); pack_hilo(hv.y, h1u, l1u);
        *(uint32_t*)(&g_hbf_hi[0][i0]) = (uint32_t)h0u | ((uint32_t)h1u << 16);
        *(uint32_t*)(&g_hbf_lo[0][i0]) = (uint32_t)l0u | ((uint32_t)l1u << 16);
    }
    // prologue barrier (all G via cnt1)
    __syncthreads();
    if (tid == 0) arrive(&g_cnt1);
    t1 += G;
    if (tid == 0) waitcnt(&g_cnt1, t1);
    __syncthreads();

    // persistent B tile -> smem
    for (int idx = tid; idx < NSL * KSL; idx += NT) {
        int n = idx >> 7, k = idx & 127;
        int src = (ntl * NSL + n) * Hn + kt * KSL + k;
        sBhi[n * PK + k] = g_WT_hi[src];
        sBlo[n * PK + k] = g_WT_lo[src];
    }

    // fragment base addresses
    const uint32_t aBaseHi = smem_u32(sAhi) +
        (uint32_t)(((m0 + (lane & 7) + ((lane >> 3) & 1) * 8) * PK + (lane >> 4) * 8) * 2);
    const uint32_t aBaseLo = aBaseHi + (uint32_t)(128 * PK * 2);
    const int nl0 = (nh * 4 + 0 + (lane >> 4)) * 8 + (lane & 7);
    const int nl1 = (nh * 4 + 2 + (lane >> 4)) * 8 + (lane & 7);
    const int bko = ((lane >> 3) & 1) * 8;
    const uint32_t bBaseHi0 = smem_u32(sBhi) + (uint32_t)((nl0 * PK + bko) * 2);
    const uint32_t bBaseHi1 = smem_u32(sBhi) + (uint32_t)((nl1 * PK + bko) * 2);
    const uint32_t bBaseLo0 = bBaseHi0 + (uint32_t)(64 * PK * 2);
    const uint32_t bBaseLo1 = bBaseHi1 + (uint32_t)(64 * PK * 2);

    // ======== recurrence: iter l consumes h_l -> partials(h_{l+1}, logits_{l-1}) ========
    for (int l = 0; l <= Ln; ++l) {
        const int c = l & 1;
        const bool doMMA = (l < Ln) || (ntl == NTL - 1);

        if (doMMA) {   // stage A slice (L2-only loads; written last step by other SMs)
#pragma unroll
            for (int it = 0; it < 4; ++it) {
                int i = (it * NT + tid) * 8;
                int row = i >> 7, k = i & 127;
                *(uint4*)(sAhi + row * PK + k) =
                    ldcg4(&g_hbf_hi[c][row * Hn + kt * KSL + k]);
                *(uint4*)(sAlo + row * PK + k) =
                    ldcg4(&g_hbf_lo[c][row * Hn + kt * KSL + k]);
            }
        }
        __syncthreads();

        if (doMMA) {
            float acc[4][4];
#pragma unroll
            for (int nt = 0; nt < 4; ++nt)
#pragma unroll
                for (int q = 0; q < 4; ++q) acc[nt][q] = 0.f;

#pragma unroll
            for (int kk = 0; kk < 8; ++kk) {
                const uint32_t ko = kk * 32;
                uint32_t ah0, ah1, ah2, ah3, al0, al1, al2, al3;
                LDSM4(ah0, ah1, ah2, ah3, aBaseHi + ko);
                LDSM4(al0, al1, al2, al3, aBaseLo + ko);
                uint32_t b00, b01, b10, b11, b20, b21, b30, b31;
                LDSM4(b00, b01, b10, b11, bBaseHi0 + ko);
                LDSM4(b20, b21, b30, b31, bBaseHi1 + ko);
                uint32_t c00, c01, c10, c11, c20, c21, c30, c31;
                LDSM4(c00, c01, c10, c11, bBaseLo0 + ko);
                LDSM4(c20, c21, c30, c31, bBaseLo1 + ko);

                MMA16816(acc[0], ah0, ah1, ah2, ah3, b00, b01);
                MMA16816(acc[1], ah0, ah1, ah2, ah3, b10, b11);
                MMA16816(acc[2], ah0, ah1, ah2, ah3, b20, b21);
                MMA16816(acc[3], ah0, ah1, ah2, ah3, b30, b31);
                MMA16816(acc[0], ah0, ah1, ah2, ah3, c00, c01);
                MMA16816(acc[1], ah0, ah1, ah2, ah3, c10, c11);
                MMA16816(acc[2], ah0, ah1, ah2, ah3, c20, c21);
                MMA16816(acc[3], ah0, ah1, ah2, ah3, c30, c31);
                MMA16816(acc[0], al0, al1, al2, al3, b00, b01);
                MMA16816(acc[1], al0, al1, al2, al3, b10, b11);
                MMA16816(acc[2], al0, al1, al2, al3, b20, b21);
                MMA16816(acc[3], al0, al1, al2, al3, b30, b31);
            }
#pragma unroll
            for (int nt = 0; nt < 4; ++nt) {
                int col = ntl * NSL + (nh * 4 + nt) * 8 + tg * 2;
                *(float2*)(&g_part[kt][m0 + gq][col])     = make_float2(acc[nt][0], acc[nt][1]);
                *(float2*)(&g_part[kt][m0 + gq + 8][col]) = make_float2(acc[nt][2], acc[nt][3]);
            }
        }

        // ---- barrier 1: partials ready (all arrive; only producers of h wait) ----
        __syncthreads();
        if (tid == 0) arrive(&g_cnt1);
        t1 += G;

        if (bid < Bn) {
            if (tid == 0) waitcnt(&g_cnt1, t1);
            __syncthreads();
            const int b = bid;
            if (l < Ln) {
                const int xv = x[b * Ln + l];
                const int h0 = tid * 2;
                float2 s = *(const float2*)(g_P + xv * Hn + h0);
#pragma unroll
                for (int j = 0; j < KSP; ++j) {
                    float2 p = ldcg2f(&g_part[j][b][h0]);
                    s.x += p.x; s.y += p.y;
                }
                float2 hv;
                hv.x = tanhf(s.x); hv.y = tanhf(s.y);
                unsigned short h0u, l0u, h1u, l1u;
                pack_hilo(hv.x, h0u, l0u); pack_hilo(hv.y, h1u, l1u);
                int i0 = b * Hn + h0;
                *(uint32_t*)(&g_hbf_hi[1 - c][i0]) = (uint32_t)h0u | ((uint32_t)h1u << 16);
                *(uint32_t*)(&g_hbf_lo[1 - c][i0]) = (uint32_t)l0u | ((uint32_t)l1u << 16);
                if (l == Ln - 1)
                    *(float2*)(outh + i0) = hv;
            }
            if (l > 0 && tid < Vn) {
                float s = bo[tid];
#pragma unroll
                for (int j = 0; j < KSP; ++j) s += ldcgf(&g_part[j][b][Hn + tid]);
                logits[((size_t)b * Ln + (l - 1)) * Vn + tid] = s;
            }
            __syncthreads();
            if (tid == 0) arrive(&g_cnt2);
        }
        t2 += Bn;

        // ---- barrier 2: new h ready (everyone waits) ----
        if (l < Ln) {
            if (tid == 0) waitcnt(&g_cnt2, t2);
            __syncthreads();
        }
    }
}

extern "C" void kernel_launch(void* const* d_in, const int* in_sizes, int n_in,
                              void* d_out, int out_size) {
    const int*   x      = (const int*)d_in[0];
    const float* hidden = (const float*)d_in[1];
    const float* emb    = (const float*)d_in[2];
    const float* We     = (const float*)d_in[3];
    const float* Wh     = (const float*)d_in[4];
    const float* bh     = (const float*)d_in[5];
    const float* Wo     = (const float*)d_in[6];
    const float* bo     = (const float*)d_in[7];

    float* logits = (float*)d_out;
    float* outh   = logits + (size_t)Bn * Ln * Vn;

    cudaFuncSetAttribute(rnn_all,
                         cudaFuncAttributeMaxDynamicSharedMemorySize, SMEM_BYTES);
    rnn_all<<<G, NT, SMEM_BYTES>>>(x, hidden, emb, We, Wh, bh, Wo, bo, logits, outh);
}